// round 10
// baseline (speedup 1.0000x reference)
#include <cuda_runtime.h>
#include <cstdint>
#include <cstddef>

#define ULL unsigned long long

__device__ __forceinline__ ULL pks(float s) {
    ULL r; asm("mov.b64 %0, {%1, %1};" : "=l"(r) : "f"(s)); return r;
}
__device__ __forceinline__ ULL pk2(float lo, float hi) {
    ULL r; asm("mov.b64 %0, {%1, %2};" : "=l"(r) : "f"(lo), "f"(hi)); return r;
}
__device__ __forceinline__ void upk(ULL v, float& lo, float& hi) {
    asm("mov.b64 {%0, %1}, %2;" : "=f"(lo), "=f"(hi) : "l"(v));
}
__device__ __forceinline__ ULL f2fma(ULL a, ULL b, ULL c) {
    ULL d; asm("fma.rn.f32x2 %0, %1, %2, %3;" : "=l"(d) : "l"(a), "l"(b), "l"(c)); return d;
}
__device__ __forceinline__ ULL f2add(ULL a, ULL b) {
    ULL d; asm("add.rn.f32x2 %0, %1, %2;" : "=l"(d) : "l"(a), "l"(b)); return d;
}
__device__ __forceinline__ float sigm(float x) { return __fdividef(1.f, 1.f + __expf(-x)); }
__device__ __forceinline__ float tanhf_(float x) {
    float ax = fabsf(x);
    float e = __expf(-2.f * ax);
    return copysignf(__fdividef(1.f - e, 1.f + e), x);
}

// ---- shared memory layout (float offsets) ----
// Half-split weight layouts: [hhalf][k...][h2l][...]
// W34: hhalf*1024 + (k*8 + h2l)*4 + {w3lo,w3hi,w4lo,w4hi}
// packed k-pair (W3U/W5U/W5A/W5B): hhalf*512 + (k2*8 + h2l)*4, j: k=2k2+(j>>1), h=2*h2+(j&1)
#define OFF_W3U  0       // 1024
#define OFF_W5U  1024    // 1024
#define OFF_W34A 2048    // 2048
#define OFF_W34B 4096    // 2048
#define OFF_W5A  6144    // 1024
#define OFF_W5B  7168    // 1024
#define OFF_WOT  8192    // 1024
#define OFF_WRXT 9216    // 512
#define OFF_WRYT 9728    // 512
#define OFF_WR2  10240   // 16
#define OFF_B3W  10256
#define OFF_B3U  10288
#define OFF_B4W  10320
#define OFF_B5W  10352
#define OFF_B5U  10384
#define OFF_BO   10416
#define OFF_BRX  10432
#define OFF_BRY  10448
#define OFF_BR2  10464   // 16
#define OFF_MB   10480   // mask bitset u32[48]
#define OFF_X0   10528   // 3072
#define OFF_NODESP 13600 // 97 x 36 (row 96 = zero)
#define OFF_AP   17092   // 96 x 36
#define OFF_MP   20548   // 96 x 36 (m; rfcx/rfcy/s reuse in readout)
#define OFF_HL   24004   // u16 headlist[16][80] = 640
#define OFF_TL   24644   // u16 taillist[80][16] = 640
#define OFF_HC   25284   // int[16]
#define OFF_TC   25300   // int[80]
#define SMEM_FLOATS 25380
#define SMEM_BYTES (SMEM_FLOATS * 4)   // 101,520 B

#define RS 36
#define RSU 18

__global__ void __launch_bounds__(256, 2)
ggnn_kernel(const float* __restrict__ xin,
            const float* __restrict__ maskg,
            const float* __restrict__ W3w, const float* __restrict__ b3w,
            const float* __restrict__ W3u, const float* __restrict__ b3u,
            const float* __restrict__ W4w, const float* __restrict__ b4w,
            const float* __restrict__ W5w, const float* __restrict__ b5w,
            const float* __restrict__ W5u, const float* __restrict__ b5u,
            const float* __restrict__ Wo,  const float* __restrict__ bo,
            const float* __restrict__ Wrx, const float* __restrict__ brx,
            const float* __restrict__ Wry, const float* __restrict__ bry,
            const float* __restrict__ Wr2, const float* __restrict__ br2,
            float* __restrict__ outp)
{
    extern __shared__ float sm[];
    const int t = threadIdx.x;
    const int b = blockIdx.x;

    // ---- stage weights (half-split layouts) + biases + x0 ----
    for (int idx = t; idx < 2048; idx += 256) {
        int hh = idx >> 10, r = idx & 1023;
        int k = r >> 5, h2li = (r >> 2) & 7, j = r & 3;
        int h = 2 * (hh * 8 + h2li) + (j & 1);
        const float* Wsrc = (j < 2) ? W3w : W4w;
        sm[OFF_W34A + idx] = Wsrc[h * 64 + k];
        sm[OFF_W34B + idx] = Wsrc[h * 64 + 32 + k];
    }
    for (int idx = t; idx < 1024; idx += 256) {
        int hh = idx >> 9, r = idx & 511;
        int k2 = r >> 5, h2li = (r >> 2) & 7, j = r & 3;
        int k = 2 * k2 + (j >> 1);
        int h = 2 * (hh * 8 + h2li) + (j & 1);
        sm[OFF_W3U + idx] = W3u[h * 32 + k];
        sm[OFF_W5U + idx] = W5u[h * 32 + k];
        sm[OFF_W5A + idx] = W5w[h * 64 + k];
        sm[OFF_W5B + idx] = W5w[h * 64 + 32 + k];
        int k2o = idx >> 4, o = idx & 15;
        sm[OFF_WOT + idx] = Wo[o * 64 + k2o];
    }
    for (int idx = t; idx < 512; idx += 256) {
        int k = idx >> 4, o = idx & 15;
        sm[OFF_WRXT + idx] = Wrx[o * 32 + k];
        sm[OFF_WRYT + idx] = Wry[o * 32 + k];
    }
    if (t < 32) {
        sm[OFF_B3W + t] = b3w[t]; sm[OFF_B3U + t] = b3u[t];
        sm[OFF_B4W + t] = b4w[t]; sm[OFF_B5W + t] = b5w[t];
        sm[OFF_B5U + t] = b5u[t];
    }
    if (t < 16) {
        sm[OFF_BO + t] = bo[t]; sm[OFF_BRX + t] = brx[t];
        sm[OFF_BRY + t] = bry[t]; sm[OFF_WR2 + t] = Wr2[t];
    }
    if (t == 0) sm[OFF_BR2] = br2[0];
    if (t < 36) sm[OFF_NODESP + 96 * RS + t] = 0.f;   // zero row (pad target)
    {
        const float4* xp = reinterpret_cast<const float4*>(xin + (size_t)b * 3072);
#pragma unroll
        for (int q = 0; q < 3; q++) {
            int idx = t + (q << 8);
            float4 v = xp[idx];
            int i = idx >> 3, kq = idx & 7;
            *reinterpret_cast<float4*>(sm + OFF_X0 + i * 32 + kq * 4) = v;
            *reinterpret_cast<float4*>(sm + OFF_NODESP + i * RS + kq * 4) = v;
        }
    }

    // ---- sparse index lists + mask bitset (from gmem) ----
    uint16_t* hl16 = reinterpret_cast<uint16_t*>(sm + OFF_HL);
    uint16_t* tl16 = reinterpret_cast<uint16_t*>(sm + OFF_TL);
    int* headcnt = reinterpret_cast<int*>(sm + OFF_HC);
    int* tailcnt = reinterpret_cast<int*>(sm + OFF_TC);
    uint32_t* mbits = reinterpret_cast<uint32_t*>(sm + OFF_MB);
    if (t < 16) {
        int c = 0;
        uint32_t w0 = 0, w1 = 0, w2 = 0;
        for (int j = 0; j < 80; j++) {
            if (maskg[t * 80 + j] != 0.f) {
                hl16[t * 80 + c++] = (uint16_t)((16 + j) * RS);
                if (j < 32) w0 |= 1u << j;
                else if (j < 64) w1 |= 1u << (j - 32);
                else w2 |= 1u << (j - 64);
            }
        }
        if (c & 1) hl16[t * 80 + c++] = (uint16_t)(96 * RS);
        headcnt[t] = c;
        mbits[t * 3 + 0] = w0; mbits[t * 3 + 1] = w1; mbits[t * 3 + 2] = w2;
    } else if (t < 96) {
        int j = t - 16, c = 0;
        for (int i = 0; i < 16; i++)
            if (maskg[i * 80 + j] != 0.f) tl16[j * 16 + c++] = (uint16_t)(i * RS);
        if (c & 1) tl16[j * 16 + c++] = (uint16_t)(96 * RS);
        tailcnt[j] = c;
    }
    __syncthreads();

    // ---- gate-phase thread mapping ----
    const int w     = t >> 5;
    const int hhalf = w & 1;
    const int nq    = w >> 1;          // node quarter 0..3
    const int h2l   = (t >> 2) & 7;
    const int h2    = hhalf * 8 + h2l;
    const int s     = t & 3;           // subset
    const int ih    = nq * 4 + s;      // head node
    int ii[6];
    ii[0] = ih;
#pragma unroll
    for (int n = 1; n < 6; n++) ii[n] = 16 + nq * 20 + (n - 1) * 4 + s;

    // per-thread weight bases (h-half split)
    const float* wb34A = sm + OFF_W34A + hhalf * 1024 + h2l * 4;
    const float* wb34B = sm + OFF_W34B + hhalf * 1024 + h2l * 4;
    const float* wbU3  = sm + OFF_W3U  + hhalf * 512  + h2l * 4;
    const float* wbU5  = sm + OFF_W5U  + hhalf * 512  + h2l * 4;
    const float* wb5A  = sm + OFF_W5A  + hhalf * 512  + h2l * 4;
    const float* wb5B  = sm + OFF_W5B  + hhalf * 512  + h2l * 4;

    ULL* nodes2p = reinterpret_cast<ULL*>(sm + OFF_NODESP);
    ULL* m2p     = reinterpret_cast<ULL*>(sm + OFF_MP);

    const ULL b3w2 = *reinterpret_cast<const ULL*>(sm + OFF_B3W + 2 * h2);
    const ULL b3u2 = *reinterpret_cast<const ULL*>(sm + OFF_B3U + 2 * h2);
    const ULL b4w2 = *reinterpret_cast<const ULL*>(sm + OFF_B4W + 2 * h2);
    const ULL b5w2 = *reinterpret_cast<const ULL*>(sm + OFF_B5W + 2 * h2);
    const ULL b5u2 = *reinterpret_cast<const ULL*>(sm + OFF_B5U + 2 * h2);

    ULL zr[6], g5r[6];

    // ================= T=5 recurrent iterations =================
#pragma unroll 1
    for (int step = 0; step < 5; step++) {
        // ---- Phase A: sparse message pass, float4 granularity ----
#pragma unroll 1
        for (int c = 0; c < 3; c++) {
            int item = t + (c << 8);
            int r = item >> 3, q = item & 7;
            int cnt;
            const uint16_t* lst;
            if (r < 16) { cnt = headcnt[r]; lst = hl16 + r * 80; }
            else        { cnt = tailcnt[r - 16]; lst = tl16 + (r - 16) * 16; }
            const float* basep = sm + OFF_NODESP + q * 4;
            ULL acc0 = 0, acc1 = 0;
            for (int ci = 0; ci < cnt; ci += 2) {
                uint32_t wv = *reinterpret_cast<const uint32_t*>(lst + ci);
                float4 v0 = *reinterpret_cast<const float4*>(basep + (wv & 0xFFFF));
                float4 v1 = *reinterpret_cast<const float4*>(basep + (wv >> 16));
                const ULL* u0 = reinterpret_cast<const ULL*>(&v0);
                const ULL* u1 = reinterpret_cast<const ULL*>(&v1);
                acc0 = f2add(acc0, u0[0]); acc1 = f2add(acc1, u0[1]);
                acc0 = f2add(acc0, u1[0]); acc1 = f2add(acc1, u1[1]);
            }
            float4 res;
            reinterpret_cast<ULL*>(&res)[0] = acc0;
            reinterpret_cast<ULL*>(&res)[1] = acc1;
            *reinterpret_cast<float4*>(sm + OFF_AP + r * RS + q * 4) = res;
        }
        __syncthreads();

        // ---- u3 pass: u3 = nodes @ W3u^T + b3u, NB=6 ----
        ULL u3r[6];
#pragma unroll
        for (int n = 0; n < 6; n++) u3r[n] = b3u2;
#pragma unroll
        for (int q = 0; q < 8; q++) {
            int k = q * 4;
            float4 n4[6];
#pragma unroll
            for (int n = 0; n < 6; n++)
                n4[n] = *reinterpret_cast<const float4*>(sm + OFF_NODESP + ii[n] * RS + k);
            float4 wua = *reinterpret_cast<const float4*>(wbU3 + (2 * q) * 32);
            float4 wub = *reinterpret_cast<const float4*>(wbU3 + (2 * q + 1) * 32);
            const ULL* wa = reinterpret_cast<const ULL*>(&wua);
            const ULL* wb = reinterpret_cast<const ULL*>(&wub);
#pragma unroll
            for (int kk = 0; kk < 4; kk++) {
                const ULL wu = (kk < 2) ? wa[kk] : wb[kk - 2];
#pragma unroll
                for (int n = 0; n < 6; n++)
                    u3r[n] = f2fma(wu, pks(reinterpret_cast<const float*>(&n4[n])[kk]), u3r[n]);
            }
        }

        // ---- head gates: NB=1, a-weight set ----
        {
            ULL g3 = b3w2, g4 = b4w2, g5 = b5w2;
#pragma unroll
            for (int q = 0; q < 8; q++) {
                int k = q * 4;
                float4 a4 = *reinterpret_cast<const float4*>(sm + OFF_AP + ih * RS + k);
                float4 w5a = *reinterpret_cast<const float4*>(wb5A + (2 * q) * 32);
                float4 w5b = *reinterpret_cast<const float4*>(wb5A + (2 * q + 1) * 32);
                const ULL* w5u0 = reinterpret_cast<const ULL*>(&w5a);
                const ULL* w5u1 = reinterpret_cast<const ULL*>(&w5b);
#pragma unroll
                for (int kk = 0; kk < 4; kk++) {
                    float4 wf = *reinterpret_cast<const float4*>(wb34A + (k + kk) * 32);
                    const ULL* wfu = reinterpret_cast<const ULL*>(&wf);
                    const ULL w5 = (kk < 2) ? w5u0[kk] : w5u1[kk - 2];
                    ULL ab = pks(reinterpret_cast<const float*>(&a4)[kk]);
                    g3 = f2fma(wfu[0], ab, g3);
                    g4 = f2fma(wfu[1], ab, g4);
                    g5 = f2fma(w5, ab, g5);
                }
            }
            ULL s3 = f2add(g3, u3r[0]), s4 = f2add(g4, u3r[0]);
            float s3x, s3y, s4x, s4y, ox, oy;
            upk(s3, s3x, s3y); upk(s4, s4x, s4y);
            upk(nodes2p[ih * RSU + h2], ox, oy);
            m2p[ih * RSU + h2] = pk2(sigm(s4x) * ox, sigm(s4y) * oy);
            zr[0] = pk2(sigm(s3x), sigm(s3y));
            g5r[0] = g5;
        }

        // ---- tail gates: NB=5, b-weight set ----
        {
            ULL g3[5], g4[5], g5[5];
#pragma unroll
            for (int n = 0; n < 5; n++) { g3[n] = b3w2; g4[n] = b4w2; g5[n] = b5w2; }
#pragma unroll
            for (int q = 0; q < 8; q++) {
                int k = q * 4;
                float4 a4[5];
#pragma unroll
                for (int n = 0; n < 5; n++)
                    a4[n] = *reinterpret_cast<const float4*>(sm + OFF_AP + ii[1 + n] * RS + k);
                float4 w5a = *reinterpret_cast<const float4*>(wb5B + (2 * q) * 32);
                float4 w5b = *reinterpret_cast<const float4*>(wb5B + (2 * q + 1) * 32);
                const ULL* w5u0 = reinterpret_cast<const ULL*>(&w5a);
                const ULL* w5u1 = reinterpret_cast<const ULL*>(&w5b);
#pragma unroll
                for (int kk = 0; kk < 4; kk++) {
                    float4 wf = *reinterpret_cast<const float4*>(wb34B + (k + kk) * 32);
                    const ULL* wfu = reinterpret_cast<const ULL*>(&wf);
                    const ULL w5 = (kk < 2) ? w5u0[kk] : w5u1[kk - 2];
#pragma unroll
                    for (int n = 0; n < 5; n++) {
                        ULL ab = pks(reinterpret_cast<const float*>(&a4[n])[kk]);
                        g3[n] = f2fma(wfu[0], ab, g3[n]);
                        g4[n] = f2fma(wfu[1], ab, g4[n]);
                        g5[n] = f2fma(w5, ab, g5[n]);
                    }
                }
            }
#pragma unroll
            for (int n = 0; n < 5; n++) {
                ULL s3 = f2add(g3[n], u3r[1 + n]), s4 = f2add(g4[n], u3r[1 + n]);
                float s3x, s3y, s4x, s4y, ox, oy;
                upk(s3, s3x, s3y); upk(s4, s4x, s4y);
                upk(nodes2p[ii[1 + n] * RSU + h2], ox, oy);
                m2p[ii[1 + n] * RSU + h2] = pk2(sigm(s4x) * ox, sigm(s4y) * oy);
                zr[1 + n] = pk2(sigm(s3x), sigm(s3y));
                g5r[1 + n] = g5[n];
            }
        }
        __syncthreads();

        // ---- B2: hv = tanh(g5 + m @ W5u^T + b5u); node update ----
        {
            ULL acc[6];
#pragma unroll
            for (int n = 0; n < 6; n++) acc[n] = b5u2;
#pragma unroll
            for (int q = 0; q < 8; q++) {
                int k = q * 4;
                float4 m4[6];
#pragma unroll
                for (int n = 0; n < 6; n++)
                    m4[n] = *reinterpret_cast<const float4*>(sm + OFF_MP + ii[n] * RS + k);
                float4 wua = *reinterpret_cast<const float4*>(wbU5 + (2 * q) * 32);
                float4 wub = *reinterpret_cast<const float4*>(wbU5 + (2 * q + 1) * 32);
                const ULL* wa = reinterpret_cast<const ULL*>(&wua);
                const ULL* wb = reinterpret_cast<const ULL*>(&wub);
#pragma unroll
                for (int kk = 0; kk < 4; kk++) {
                    const ULL wv = (kk < 2) ? wa[kk] : wb[kk - 2];
#pragma unroll
                    for (int n = 0; n < 6; n++)
                        acc[n] = f2fma(wv, pks(reinterpret_cast<const float*>(&m4[n])[kk]), acc[n]);
                }
            }
#pragma unroll
            for (int n = 0; n < 6; n++) {
                ULL hpre = f2add(g5r[n], acc[n]);
                float hx, hy, ox, oy, zx, zy;
                upk(hpre, hx, hy);
                upk(nodes2p[ii[n] * RSU + h2], ox, oy);
                upk(zr[n], zx, zy);
                hx = tanhf_(hx); hy = tanhf_(hy);
                nodes2p[ii[n] * RSU + h2] = pk2(fmaf(zx, hx - ox, ox), fmaf(zy, hy - oy, oy));
            }
        }
        __syncthreads();
    }

    // ================= readout =================
    // F0: out[96][16] -> AP region (dense [i][16])
#pragma unroll 1
    for (int q = 0; q < 6; q++) {
        int item = t + (q << 8);
        int i = item >> 4, o = item & 15;
        const float* nrow = sm + OFF_NODESP + i * RS;
        const float* xrow = sm + OFF_X0 + i * 32;
        float acc0 = sm[OFF_BO + o], acc1 = 0.f;
#pragma unroll
        for (int k = 0; k < 32; k++) {
            acc0 = fmaf(sm[OFF_WOT + k * 16 + o], nrow[k], acc0);
            acc1 = fmaf(sm[OFF_WOT + (32 + k) * 16 + o], xrow[k], acc1);
        }
        sm[OFF_AP + i * 16 + o] = tanhf_(acc0 + acc1);
    }
    // F1: rfcx[16][16] at MP (stride 16); rfcy[80] at MP+256 (stride 17)
    {
        int i = t >> 4, o = t & 15;
        const float* nrow = sm + OFF_NODESP + i * RS;
        float acc = sm[OFF_BRX + o];
#pragma unroll
        for (int k = 0; k < 32; k++) acc = fmaf(sm[OFF_WRXT + k * 16 + o], nrow[k], acc);
        sm[OFF_MP + i * 16 + o] = tanhf_(acc);
    }
#pragma unroll 1
    for (int q = 1; q < 6; q++) {
        int item = t + (q << 8);
        int j = (item - 256) >> 4, o = item & 15;
        const float* nrow = sm + OFF_NODESP + (16 + j) * RS;
        float acc = sm[OFF_BRY + o];
#pragma unroll
        for (int k = 0; k < 32; k++) acc = fmaf(sm[OFF_WRYT + k * 16 + o], nrow[k], acc);
        sm[OFF_MP + 256 + j * 17 + o] = tanhf_(acc);
    }
    __syncthreads();

    // F2: s[i][j] = sigmoid(sum_o Wr2[o]*rfcx[i,o]*rfcy[j,o] + br2) * mask[i][j]
#pragma unroll 1
    for (int q = 0; q < 5; q++) {
        int item = t + (q << 8);
        int i = item / 80;
        int j = item - i * 80;
        const float* rx = sm + OFF_MP + i * 16;
        const float* ry = sm + OFF_MP + 256 + j * 17;
        float acc = sm[OFF_BR2];
#pragma unroll
        for (int o = 0; o < 16; o++) acc = fmaf(sm[OFF_WR2 + o] * rx[o], ry[o], acc);
        uint32_t mb = mbits[i * 3 + (j >> 5)];
        float msk = (float)((mb >> (j & 31)) & 1u);
        sm[OFF_MP + 1616 + item] = sigm(acc) * msk;
    }
    __syncthreads();

    // Final write
    {
        float4* og = reinterpret_cast<float4*>(outp) + (size_t)b * 5184;
#pragma unroll 1
        for (int q = 0; q < 21; q++) {
            int idx = t + (q << 8);
            if (idx < 5184) {
                int i = idx / 324;
                int rem = idx - i * 324;
                int k = rem >> 2, o4 = rem & 3;
                float4 v;
                if (k == 0) {
                    v = *reinterpret_cast<const float4*>(sm + OFF_AP + i * 16 + o4 * 4);
                } else {
                    int j = k - 1;
                    float sv = sm[OFF_MP + 1616 + i * 80 + j];
                    float4 u = *reinterpret_cast<const float4*>(sm + OFF_AP + (16 + j) * 16 + o4 * 4);
                    v = make_float4(u.x * sv, u.y * sv, u.z * sv, u.w * sv);
                }
                og[idx] = v;
            }
        }
    }
}

extern "C" void kernel_launch(void* const* d_in, const int* in_sizes, int n_in,
                              void* d_out, int out_size) {
    (void)in_sizes; (void)n_in; (void)out_size;
    cudaFuncSetAttribute(ggnn_kernel, cudaFuncAttributeMaxDynamicSharedMemorySize, SMEM_BYTES);
    ggnn_kernel<<<4096, 256, SMEM_BYTES>>>(
        (const float*)d_in[0],              // input
        (const float*)d_in[3],              // mask
        (const float*)d_in[4],  (const float*)d_in[5],   // W3w, b3w
        (const float*)d_in[6],  (const float*)d_in[7],   // W3u, b3u
        (const float*)d_in[8],  (const float*)d_in[9],   // W4w, b4w
        (const float*)d_in[10], (const float*)d_in[11],  // W5w, b5w
        (const float*)d_in[12], (const float*)d_in[13],  // W5u, b5u
        (const float*)d_in[14], (const float*)d_in[15],  // Wo, bo
        (const float*)d_in[16], (const float*)d_in[17],  // Wrx, brx
        (const float*)d_in[18], (const float*)d_in[19],  // Wry, bry
        (const float*)d_in[20], (const float*)d_in[21],  // Wr2, br2
        (float*)d_out);
}

// round 12
// speedup vs baseline: 1.0623x; 1.0623x over previous
#include <cuda_runtime.h>
#include <cstdint>
#include <cstddef>

#define ULL unsigned long long

__device__ __forceinline__ ULL pks(float s) {
    ULL r; asm("mov.b64 %0, {%1, %1};" : "=l"(r) : "f"(s)); return r;
}
__device__ __forceinline__ ULL pk2(float lo, float hi) {
    ULL r; asm("mov.b64 %0, {%1, %2};" : "=l"(r) : "f"(lo), "f"(hi)); return r;
}
__device__ __forceinline__ void upk(ULL v, float& lo, float& hi) {
    asm("mov.b64 {%0, %1}, %2;" : "=f"(lo), "=f"(hi) : "l"(v));
}
__device__ __forceinline__ ULL f2fma(ULL a, ULL b, ULL c) {
    ULL d; asm("fma.rn.f32x2 %0, %1, %2, %3;" : "=l"(d) : "l"(a), "l"(b), "l"(c)); return d;
}
__device__ __forceinline__ ULL f2add(ULL a, ULL b) {
    ULL d; asm("add.rn.f32x2 %0, %1, %2;" : "=l"(d) : "l"(a), "l"(b)); return d;
}
// fp16x2 word -> packed f32x2 (lo half -> lo float)
__device__ __forceinline__ ULL h2f2(uint32_t w) {
    float lo, hi;
    asm("{\n\t.reg .f16 l, h;\n\tmov.b32 {l, h}, %2;\n\tcvt.f32.f16 %0, l;\n\tcvt.f32.f16 %1, h;\n\t}"
        : "=f"(lo), "=f"(hi) : "r"(w));
    return pk2(lo, hi);
}
__device__ __forceinline__ uint32_t f2h2(float lo, float hi) {
    uint32_t r; asm("cvt.rn.f16x2.f32 %0, %1, %2;" : "=r"(r) : "f"(hi), "f"(lo)); return r;
}
__device__ __forceinline__ float sigm(float x) { return __fdividef(1.f, 1.f + __expf(-x)); }
__device__ __forceinline__ float tanhf_(float x) {
    float ax = fabsf(x);
    float e = __expf(-2.f * ax);
    return copysignf(__fdividef(1.f - e, 1.f + e), x);
}

// ---- shared memory layout (float offsets) ----
// k-pair packed u-style weights: P[(k2*16+h2)*4 + j]: k=2*k2+(j>>1), h=2*h2+(j&1)
#define OFF_W3U  0       // 1024
#define OFF_W5U  1024    // 1024
#define OFF_W34A 2048    // [k][h2][w3lo,w3hi,w4lo,w4hi] 2048
#define OFF_W34B 4096    // 2048
#define OFF_W5A  6144    // 1024
#define OFF_W5B  7168    // 1024
#define OFF_WOT  8192    // 1024
#define OFF_WRXT 9216    // 512
#define OFF_WRYT 9728    // 512
#define OFF_WR2  10240   // 16
#define OFF_B3W  10256
#define OFF_B3U  10288
#define OFF_B4W  10320
#define OFF_B5W  10352
#define OFF_B5U  10384
#define OFF_BO   10416
#define OFF_BRX  10432
#define OFF_BRY  10448
#define OFF_BR2  10464   // 16
#define OFF_MB   10480   // mask bitset u32[48]
#define OFF_X0   10528   // 3072
#define OFF_NODESP 13600 // 97 x 36 fp32 (row 96 = zero)
#define OFF_AP   17092   // 96 x 36 (a-values; z parked here after gates)
#define OFF_MP   20548   // 96 x 36 (m; rfcx/rfcy/s reuse in readout)
#define OFF_NH16 24004   // fp16 nodes copy: 97 rows x 80 bytes = 1940 floats
#define OFF_HL   25944   // u16 headlist[16][80] byte-offsets = 640 floats
#define OFF_TL   26584   // u16 taillist[80][16] = 640 floats
#define OFF_HC   27224   // int[16]
#define OFF_TC   27240   // int[80]
#define SMEM_FLOATS 27320
#define SMEM_BYTES (SMEM_FLOATS * 4)   // 109,280 B (2 CTAs/SM)

#define RS 36
#define RSU 18
#define NBROW 80   // fp16 copy row stride in bytes (64B data + 16B pad)

__global__ void __launch_bounds__(256, 2)
ggnn_kernel(const float* __restrict__ xin,
            const float* __restrict__ maskg,
            const float* __restrict__ W3w, const float* __restrict__ b3w,
            const float* __restrict__ W3u, const float* __restrict__ b3u,
            const float* __restrict__ W4w, const float* __restrict__ b4w,
            const float* __restrict__ W5w, const float* __restrict__ b5w,
            const float* __restrict__ W5u, const float* __restrict__ b5u,
            const float* __restrict__ Wo,  const float* __restrict__ bo,
            const float* __restrict__ Wrx, const float* __restrict__ brx,
            const float* __restrict__ Wry, const float* __restrict__ bry,
            const float* __restrict__ Wr2, const float* __restrict__ br2,
            float* __restrict__ outp)
{
    extern __shared__ float sm[];
    const int t = threadIdx.x;
    const int b = blockIdx.x;
    char* nh16 = reinterpret_cast<char*>(sm + OFF_NH16);

    // ---- stage weights + biases + x0 ----
    for (int idx = t; idx < 2048; idx += 256) {
        int quad = idx >> 2, q = idx & 3;
        int k = quad >> 4, h2i = quad & 15;
        int h = 2 * h2i + (q & 1);
        const float* Wsrc = (q < 2) ? W3w : W4w;
        sm[OFF_W34A + idx] = Wsrc[h * 64 + k];
        sm[OFF_W34B + idx] = Wsrc[h * 64 + 32 + k];
    }
    for (int idx = t; idx < 1024; idx += 256) {
        int j = idx & 3, h2i = (idx >> 2) & 15, k2 = idx >> 6;
        int k = 2 * k2 + (j >> 1), h = 2 * h2i + (j & 1);
        sm[OFF_W3U + idx] = W3u[h * 32 + k];
        sm[OFF_W5U + idx] = W5u[h * 32 + k];
        sm[OFF_W5A + idx] = W5w[h * 64 + k];
        sm[OFF_W5B + idx] = W5w[h * 64 + 32 + k];
        int k2o = idx >> 4, o = idx & 15;
        sm[OFF_WOT + idx] = Wo[o * 64 + k2o];
    }
    for (int idx = t; idx < 512; idx += 256) {
        int k = idx >> 4, o = idx & 15;
        sm[OFF_WRXT + idx] = Wrx[o * 32 + k];
        sm[OFF_WRYT + idx] = Wry[o * 32 + k];
    }
    if (t < 32) {
        sm[OFF_B3W + t] = b3w[t]; sm[OFF_B3U + t] = b3u[t];
        sm[OFF_B4W + t] = b4w[t]; sm[OFF_B5W + t] = b5w[t];
        sm[OFF_B5U + t] = b5u[t];
    }
    if (t < 16) {
        sm[OFF_BO + t] = bo[t]; sm[OFF_BRX + t] = brx[t];
        sm[OFF_BRY + t] = bry[t]; sm[OFF_WR2 + t] = Wr2[t];
    }
    if (t == 0) sm[OFF_BR2] = br2[0];
    if (t < 36) sm[OFF_NODESP + 96 * RS + t] = 0.f;      // fp32 zero row
    if (t < 20) reinterpret_cast<uint32_t*>(nh16 + 96 * NBROW)[t] = 0u;  // fp16 zero row
    {
        const float4* xp = reinterpret_cast<const float4*>(xin + (size_t)b * 3072);
#pragma unroll
        for (int q = 0; q < 3; q++) {
            int idx = t + (q << 8);
            float4 v = xp[idx];
            int i = idx >> 3, kq = idx & 7;
            *reinterpret_cast<float4*>(sm + OFF_X0 + i * 32 + kq * 4) = v;
            *reinterpret_cast<float4*>(sm + OFF_NODESP + i * RS + kq * 4) = v;
            uint32_t lo = f2h2(v.x, v.y), hi = f2h2(v.z, v.w);
            *reinterpret_cast<ULL*>(nh16 + i * NBROW + kq * 8) = ((ULL)hi << 32) | lo;
        }
    }

    // ---- sparse index lists (u16 = fp16-copy row byte-offsets) + mask bitset ----
    uint16_t* hl16 = reinterpret_cast<uint16_t*>(sm + OFF_HL);
    uint16_t* tl16 = reinterpret_cast<uint16_t*>(sm + OFF_TL);
    int* headcnt = reinterpret_cast<int*>(sm + OFF_HC);
    int* tailcnt = reinterpret_cast<int*>(sm + OFF_TC);
    uint32_t* mbits = reinterpret_cast<uint32_t*>(sm + OFF_MB);
    if (t < 16) {
        int c = 0;
        uint32_t w0 = 0, w1 = 0, w2 = 0;
        for (int j = 0; j < 80; j++) {
            if (maskg[t * 80 + j] != 0.f) {
                hl16[t * 80 + c++] = (uint16_t)((16 + j) * NBROW);
                if (j < 32) w0 |= 1u << j;
                else if (j < 64) w1 |= 1u << (j - 32);
                else w2 |= 1u << (j - 64);
            }
        }
        if (c & 1) hl16[t * 80 + c++] = (uint16_t)(96 * NBROW);
        headcnt[t] = c;
        mbits[t * 3 + 0] = w0; mbits[t * 3 + 1] = w1; mbits[t * 3 + 2] = w2;
    } else if (t < 96) {
        int j = t - 16, c = 0;
        for (int i = 0; i < 16; i++)
            if (maskg[i * 80 + j] != 0.f) tl16[j * 16 + c++] = (uint16_t)(i * NBROW);
        if (c & 1) tl16[j * 16 + c++] = (uint16_t)(96 * NBROW);
        tailcnt[j] = c;
    }
    __syncthreads();

    const int h2 = t & 15;
    const int g  = t >> 4;
    const int it0 = 16 + g * 5;
    const int ii[6] = { g, it0, it0 + 1, it0 + 2, it0 + 3, it0 + 4 };

    ULL* nodes2p = reinterpret_cast<ULL*>(sm + OFF_NODESP);
    ULL* a2p     = reinterpret_cast<ULL*>(sm + OFF_AP);
    ULL* m2p     = reinterpret_cast<ULL*>(sm + OFF_MP);

    // ================= T=5 recurrent iterations =================
#pragma unroll 1
    for (int step = 0; step < 5; step++) {
        // ---- Phase A: sparse message pass from fp16 node copy ----
#pragma unroll 1
        for (int c = 0; c < 3; c++) {
            int item = t + (c << 8);
            int r = item >> 3, q = item & 7;
            int cnt;
            const uint16_t* lst;
            if (r < 16) { cnt = headcnt[r]; lst = hl16 + r * 80; }
            else        { cnt = tailcnt[r - 16]; lst = tl16 + (r - 16) * 16; }
            const char* nbq = nh16 + q * 8;
            ULL acc0 = 0, acc1 = 0;
            for (int ci = 0; ci < cnt; ci += 2) {
                uint32_t wv = *reinterpret_cast<const uint32_t*>(lst + ci);
                ULL p0 = *reinterpret_cast<const ULL*>(nbq + (wv & 0xFFFF));
                ULL p1 = *reinterpret_cast<const ULL*>(nbq + (wv >> 16));
                acc0 = f2add(acc0, h2f2((uint32_t)p0));
                acc1 = f2add(acc1, h2f2((uint32_t)(p0 >> 32)));
                acc0 = f2add(acc0, h2f2((uint32_t)p1));
                acc1 = f2add(acc1, h2f2((uint32_t)(p1 >> 32)));
            }
            float4 res;
            reinterpret_cast<ULL*>(&res)[0] = acc0;
            reinterpret_cast<ULL*>(&res)[1] = acc1;
            *reinterpret_cast<float4*>(sm + OFF_AP + r * RS + q * 4) = res;
        }
        __syncthreads();

        // ---- B1a: u3 = nodes @ W3u^T + b3u (NB=6) ----
        ULL u3r[6];
        {
            const ULL b3u2 = *reinterpret_cast<const ULL*>(sm + OFF_B3U + 2 * h2);
#pragma unroll
            for (int n = 0; n < 6; n++) u3r[n] = b3u2;
#pragma unroll
            for (int q = 0; q < 8; q++) {
                int k = q * 4;
                float4 n4[6];
#pragma unroll
                for (int n = 0; n < 6; n++)
                    n4[n] = *reinterpret_cast<const float4*>(sm + OFF_NODESP + ii[n] * RS + k);
                float4 wua = *reinterpret_cast<const float4*>(sm + OFF_W3U + ((2 * q) * 16 + h2) * 4);
                float4 wub = *reinterpret_cast<const float4*>(sm + OFF_W3U + ((2 * q + 1) * 16 + h2) * 4);
                const ULL* wa = reinterpret_cast<const ULL*>(&wua);
                const ULL* wb = reinterpret_cast<const ULL*>(&wub);
#pragma unroll
                for (int kk = 0; kk < 4; kk++) {
                    const ULL wu = (kk < 2) ? wa[kk] : wb[kk - 2];
#pragma unroll
                    for (int n = 0; n < 6; n++)
                        u3r[n] = f2fma(wu, pks(reinterpret_cast<const float*>(&n4[n])[kk]), u3r[n]);
                }
            }
        }

        ULL g5r[6];
        // ---- B1b: head gates (NB=1, a-weight set) ----
        {
            ULL g3 = *reinterpret_cast<const ULL*>(sm + OFF_B3W + 2 * h2);
            ULL g4 = *reinterpret_cast<const ULL*>(sm + OFF_B4W + 2 * h2);
            ULL g5 = *reinterpret_cast<const ULL*>(sm + OFF_B5W + 2 * h2);
#pragma unroll
            for (int q = 0; q < 8; q++) {
                int k = q * 4;
                float4 a4 = *reinterpret_cast<const float4*>(sm + OFF_AP + g * RS + k);
                float4 w5a = *reinterpret_cast<const float4*>(sm + OFF_W5A + ((2 * q) * 16 + h2) * 4);
                float4 w5b = *reinterpret_cast<const float4*>(sm + OFF_W5A + ((2 * q + 1) * 16 + h2) * 4);
                const ULL* w5u0 = reinterpret_cast<const ULL*>(&w5a);
                const ULL* w5u1 = reinterpret_cast<const ULL*>(&w5b);
#pragma unroll
                for (int kk = 0; kk < 4; kk++) {
                    float4 wf = *reinterpret_cast<const float4*>(sm + OFF_W34A + ((k + kk) * 16 + h2) * 4);
                    const ULL* wfu = reinterpret_cast<const ULL*>(&wf);
                    const ULL w5 = (kk < 2) ? w5u0[kk] : w5u1[kk - 2];
                    ULL ab = pks(reinterpret_cast<const float*>(&a4)[kk]);
                    g3 = f2fma(wfu[0], ab, g3);
                    g4 = f2fma(wfu[1], ab, g4);
                    g5 = f2fma(w5, ab, g5);
                }
            }
            ULL s3 = f2add(g3, u3r[0]), s4 = f2add(g4, u3r[0]);
            float s3x, s3y, s4x, s4y, ox, oy;
            upk(s3, s3x, s3y); upk(s4, s4x, s4y);
            upk(nodes2p[g * RSU + h2], ox, oy);
            m2p[g * RSU + h2] = pk2(sigm(s4x) * ox, sigm(s4y) * oy);
            a2p[g * RSU + h2] = pk2(sigm(s3x), sigm(s3y));   // park z
            g5r[0] = g5;
        }

        // ---- B1c: tail gates (NB=5, b-weight set) ----
        {
            ULL g3[5], g4[5];
            {
                const ULL b3w2 = *reinterpret_cast<const ULL*>(sm + OFF_B3W + 2 * h2);
                const ULL b4w2 = *reinterpret_cast<const ULL*>(sm + OFF_B4W + 2 * h2);
                const ULL b5w2 = *reinterpret_cast<const ULL*>(sm + OFF_B5W + 2 * h2);
#pragma unroll
                for (int n = 0; n < 5; n++) { g3[n] = b3w2; g4[n] = b4w2; g5r[1 + n] = b5w2; }
            }
#pragma unroll
            for (int q = 0; q < 8; q++) {
                int k = q * 4;
                float4 a4[5];
#pragma unroll
                for (int n = 0; n < 5; n++)
                    a4[n] = *reinterpret_cast<const float4*>(sm + OFF_AP + (it0 + n) * RS + k);
                float4 w5a = *reinterpret_cast<const float4*>(sm + OFF_W5B + ((2 * q) * 16 + h2) * 4);
                float4 w5b = *reinterpret_cast<const float4*>(sm + OFF_W5B + ((2 * q + 1) * 16 + h2) * 4);
                const ULL* w5u0 = reinterpret_cast<const ULL*>(&w5a);
                const ULL* w5u1 = reinterpret_cast<const ULL*>(&w5b);
#pragma unroll
                for (int kk = 0; kk < 4; kk++) {
                    float4 wf = *reinterpret_cast<const float4*>(sm + OFF_W34B + ((k + kk) * 16 + h2) * 4);
                    const ULL* wfu = reinterpret_cast<const ULL*>(&wf);
                    const ULL w5 = (kk < 2) ? w5u0[kk] : w5u1[kk - 2];
#pragma unroll
                    for (int n = 0; n < 5; n++) {
                        ULL ab = pks(reinterpret_cast<const float*>(&a4[n])[kk]);
                        g3[n] = f2fma(wfu[0], ab, g3[n]);
                        g4[n] = f2fma(wfu[1], ab, g4[n]);
                        g5r[1 + n] = f2fma(w5, ab, g5r[1 + n]);
                    }
                }
            }
#pragma unroll
            for (int n = 0; n < 5; n++) {
                ULL s3 = f2add(g3[n], u3r[1 + n]), s4 = f2add(g4[n], u3r[1 + n]);
                float s3x, s3y, s4x, s4y, ox, oy;
                upk(s3, s3x, s3y); upk(s4, s4x, s4y);
                upk(nodes2p[(it0 + n) * RSU + h2], ox, oy);
                m2p[(it0 + n) * RSU + h2] = pk2(sigm(s4x) * ox, sigm(s4y) * oy);
                a2p[(it0 + n) * RSU + h2] = pk2(sigm(s3x), sigm(s3y));  // park z
            }
        }
        __syncthreads();

        // ---- B2: hv = tanh(g5 + m @ W5u^T + b5u); node update (+fp16 copy) ----
        {
            ULL acc[6];
            const ULL b5u2 = *reinterpret_cast<const ULL*>(sm + OFF_B5U + 2 * h2);
#pragma unroll
            for (int n = 0; n < 6; n++) acc[n] = b5u2;
#pragma unroll
            for (int q = 0; q < 8; q++) {
                int k = q * 4;
                float4 m4[6];
#pragma unroll
                for (int n = 0; n < 6; n++)
                    m4[n] = *reinterpret_cast<const float4*>(sm + OFF_MP + ii[n] * RS + k);
                float4 wua = *reinterpret_cast<const float4*>(sm + OFF_W5U + ((2 * q) * 16 + h2) * 4);
                float4 wub = *reinterpret_cast<const float4*>(sm + OFF_W5U + ((2 * q + 1) * 16 + h2) * 4);
                const ULL* wa = reinterpret_cast<const ULL*>(&wua);
                const ULL* wb = reinterpret_cast<const ULL*>(&wub);
#pragma unroll
                for (int kk = 0; kk < 4; kk++) {
                    const ULL wv = (kk < 2) ? wa[kk] : wb[kk - 2];
#pragma unroll
                    for (int n = 0; n < 6; n++)
                        acc[n] = f2fma(wv, pks(reinterpret_cast<const float*>(&m4[n])[kk]), acc[n]);
                }
            }
#pragma unroll
            for (int n = 0; n < 6; n++) {
                ULL hpre = f2add(g5r[n], acc[n]);
                float hx, hy, ox, oy, zx, zy;
                upk(hpre, hx, hy);
                upk(nodes2p[ii[n] * RSU + h2], ox, oy);
                upk(a2p[ii[n] * RSU + h2], zx, zy);   // z parked in AP
                hx = tanhf_(hx); hy = tanhf_(hy);
                float nx = fmaf(zx, hx - ox, ox), ny = fmaf(zy, hy - oy, oy);
                nodes2p[ii[n] * RSU + h2] = pk2(nx, ny);
                *reinterpret_cast<uint32_t*>(nh16 + ii[n] * NBROW + h2 * 4) = f2h2(nx, ny);
            }
        }
        __syncthreads();
    }

    // ================= readout =================
#pragma unroll 1
    for (int q = 0; q < 6; q++) {
        int item = t + (q << 8);
        int i = item >> 4, o = item & 15;
        const float* nrow = sm + OFF_NODESP + i * RS;
        const float* xrow = sm + OFF_X0 + i * 32;
        float acc0 = sm[OFF_BO + o], acc1 = 0.f;
#pragma unroll
        for (int k = 0; k < 32; k++) {
            acc0 = fmaf(sm[OFF_WOT + k * 16 + o], nrow[k], acc0);
            acc1 = fmaf(sm[OFF_WOT + (32 + k) * 16 + o], xrow[k], acc1);
        }
        sm[OFF_AP + i * 16 + o] = tanhf_(acc0 + acc1);
    }
    {
        int i = t >> 4, o = t & 15;
        const float* nrow = sm + OFF_NODESP + i * RS;
        float acc = sm[OFF_BRX + o];
#pragma unroll
        for (int k = 0; k < 32; k++) acc = fmaf(sm[OFF_WRXT + k * 16 + o], nrow[k], acc);
        sm[OFF_MP + i * 16 + o] = tanhf_(acc);
    }
#pragma unroll 1
    for (int q = 1; q < 6; q++) {
        int item = t + (q << 8);
        int j = (item - 256) >> 4, o = item & 15;
        const float* nrow = sm + OFF_NODESP + (16 + j) * RS;
        float acc = sm[OFF_BRY + o];
#pragma unroll
        for (int k = 0; k < 32; k++) acc = fmaf(sm[OFF_WRYT + k * 16 + o], nrow[k], acc);
        sm[OFF_MP + 256 + j * 17 + o] = tanhf_(acc);
    }
    __syncthreads();

#pragma unroll 1
    for (int q = 0; q < 5; q++) {
        int item = t + (q << 8);
        int i = item / 80;
        int j = item - i * 80;
        const float* rx = sm + OFF_MP + i * 16;
        const float* ry = sm + OFF_MP + 256 + j * 17;
        float acc = sm[OFF_BR2];
#pragma unroll
        for (int o = 0; o < 16; o++) acc = fmaf(sm[OFF_WR2 + o] * rx[o], ry[o], acc);
        uint32_t mb = reinterpret_cast<uint32_t*>(sm + OFF_MB)[i * 3 + (j >> 5)];
        float msk = (float)((mb >> (j & 31)) & 1u);
        sm[OFF_MP + 1616 + item] = sigm(acc) * msk;
    }
    __syncthreads();

    {
        float4* og = reinterpret_cast<float4*>(outp) + (size_t)b * 5184;
#pragma unroll 1
        for (int q = 0; q < 21; q++) {
            int idx = t + (q << 8);
            if (idx < 5184) {
                int i = idx / 324;
                int rem = idx - i * 324;
                int k = rem >> 2, o4 = rem & 3;
                float4 v;
                if (k == 0) {
                    v = *reinterpret_cast<const float4*>(sm + OFF_AP + i * 16 + o4 * 4);
                } else {
                    int j = k - 1;
                    float sv = sm[OFF_MP + 1616 + i * 80 + j];
                    float4 u = *reinterpret_cast<const float4*>(sm + OFF_AP + (16 + j) * 16 + o4 * 4);
                    v = make_float4(u.x * sv, u.y * sv, u.z * sv, u.w * sv);
                }
                og[idx] = v;
            }
        }
    }
}

extern "C" void kernel_launch(void* const* d_in, const int* in_sizes, int n_in,
                              void* d_out, int out_size) {
    (void)in_sizes; (void)n_in; (void)out_size;
    cudaFuncSetAttribute(ggnn_kernel, cudaFuncAttributeMaxDynamicSharedMemorySize, SMEM_BYTES);
    ggnn_kernel<<<4096, 256, SMEM_BYTES>>>(
        (const float*)d_in[0],              // input
        (const float*)d_in[3],              // mask
        (const float*)d_in[4],  (const float*)d_in[5],   // W3w, b3w
        (const float*)d_in[6],  (const float*)d_in[7],   // W3u, b3u
        (const float*)d_in[8],  (const float*)d_in[9],   // W4w, b4w
        (const float*)d_in[10], (const float*)d_in[11],  // W5w, b5w
        (const float*)d_in[12], (const float*)d_in[13],  // W5u, b5u
        (const float*)d_in[14], (const float*)d_in[15],  // Wo, bo
        (const float*)d_in[16], (const float*)d_in[17],  // Wrx, brx
        (const float*)d_in[18], (const float*)d_in[19],  // Wry, bry
        (const float*)d_in[20], (const float*)d_in[21],  // Wr2, br2
        (float*)d_out);
}